// round 14
// baseline (speedup 1.0000x reference)
#include <cuda_runtime.h>
#include <cuda_bf16.h>
#include <math.h>
#include <stdint.h>

#define B 64
#define T 4096

// ---------------- device scratch (static only) ----------------
__device__ float g_demo_enc[B * 32];
__device__ float g_We[32 * 4];
__device__ float g_pS[(size_t)B * 32 * 4 * 128];       // per-tile partial sums (4MB)
__device__ float g_pMZ[B * 32 * 8];                    // per-tile {M[4], Z[4]}
// W1: SW64 image [128 n][32 k] (64B rows); W2/W3: SW128 images, 2 k-subtiles
__device__ __align__(16) __nv_bfloat16 g_W1h[4096],  g_W1l[4096];
__device__ __align__(16) __nv_bfloat16 g_W2h[16384], g_W2l[16384];
__device__ __align__(16) __nv_bfloat16 g_W3h[16384], g_W3l[16384];

// ---------------- helpers ----------------
__device__ __forceinline__ uint32_t smem_u32(const void* p) {
    uint32_t a;
    asm("{ .reg .u64 t; cvta.to.shared.u64 t, %1; cvt.u32.u64 %0, t; }" : "=r"(a) : "l"(p));
    return a;
}
#define SWZ128(o) ((o) ^ (((o) >> 3) & 0x70))
#define SWZ64(o)  ((o) ^ (((o) >> 3) & 0x30))

#define LDMX4(r0, r1, r2, r3, a) \
    asm volatile("ldmatrix.sync.aligned.m8n8.x4.shared.b16 {%0,%1,%2,%3}, [%4];" \
                 : "=r"(r0), "=r"(r1), "=r"(r2), "=r"(r3) : "r"(a))

#define MMA(d, a0, a1, a2, a3, b0, b1) \
    asm volatile("mma.sync.aligned.m16n8k16.row.col.f32.bf16.bf16.f32 " \
                 "{%0,%1,%2,%3}, {%4,%5,%6,%7}, {%8,%9}, {%0,%1,%2,%3};" \
                 : "+f"((d).x), "+f"((d).y), "+f"((d).z), "+f"((d).w) \
                 : "r"(a0), "r"(a1), "r"(a2), "r"(a3), "r"(b0), "r"(b1))

#define CP_ASYNC16(sma, gp) \
    asm volatile("cp.async.cg.shared.global [%0], [%1], 16;" :: "r"(sma), "l"(gp))
#define CP_COMMIT() asm volatile("cp.async.commit_group;" ::: "memory")
#define CP_WAIT(n)  asm volatile("cp.async.wait_group %0;" :: "n"(n) : "memory")

// A tile (128 rows): bf16, 2 k-subtiles of 16KB; elem (row,k) at
//   sub*16384 + SWZ128(row*128 + (k&63)*2).
// W2/W3 tile: hi at base (2 subtiles of 16KB), lo at +32768.
// W1 tile (in A subtile1 during layer 1): 64B rows, SW64; hi at base, lo at +8192.

// ---- GEMM layer on SW128 W: acc[16] += A(128xK) @ (Wh+Wl) ----
__device__ __forceinline__ void mma_layer(float4 acc[16], uint32_t aB, uint32_t wB,
                                          int wid, int lane, int kchunks)
{
    int arow = wid * 16 + (lane & 15);
    int aksel = (lane >> 4) << 3;
    int wrow = (lane & 7) + ((lane >> 4) & 1) * 8;
    int wksel = ((lane >> 3) & 1) << 3;

    for (int kc = 0; kc < kchunks; ++kc) {
        int ak = kc * 16 + aksel;
        uint32_t aOff = (uint32_t)((ak >> 6) * 16384) +
                        SWZ128((uint32_t)(arow * 128 + (ak & 63) * 2));
        uint32_t ah0, ah1, ah2, ah3;
        LDMX4(ah0, ah1, ah2, ah3, aB + aOff);

        int wk = kc * 16 + wksel;
        uint32_t wsub = (uint32_t)((wk >> 6) * 16384);
        uint32_t wko = (uint32_t)((wk & 63) * 2);

        #pragma unroll
        for (int gq = 0; gq < 4; ++gq) {
            int n0 = gq * 32 + wrow;
            uint32_t w0 = wB + wsub + SWZ128((uint32_t)(n0 * 128) + wko);
            uint32_t w1 = wB + wsub + SWZ128((uint32_t)((n0 + 16) * 128) + wko);
            uint32_t h0, h1, h2, h3, h4, h5, h6, h7;
            uint32_t l0, l1, l2, l3, l4, l5, l6, l7;
            LDMX4(h0, h1, h2, h3, w0);
            LDMX4(h4, h5, h6, h7, w1);
            LDMX4(l0, l1, l2, l3, w0 + 32768);
            LDMX4(l4, l5, l6, l7, w1 + 32768);
            MMA(acc[4 * gq + 0], ah0, ah1, ah2, ah3, h0, h1);
            MMA(acc[4 * gq + 1], ah0, ah1, ah2, ah3, h2, h3);
            MMA(acc[4 * gq + 2], ah0, ah1, ah2, ah3, h4, h5);
            MMA(acc[4 * gq + 3], ah0, ah1, ah2, ah3, h6, h7);
            MMA(acc[4 * gq + 0], ah0, ah1, ah2, ah3, l0, l1);
            MMA(acc[4 * gq + 1], ah0, ah1, ah2, ah3, l2, l3);
            MMA(acc[4 * gq + 2], ah0, ah1, ah2, ah3, l4, l5);
            MMA(acc[4 * gq + 3], ah0, ah1, ah2, ah3, l6, l7);
        }
    }
}

// ---- layer-1 GEMM on SW64 compact W1 (K=32) ----
__device__ __forceinline__ void mma_layer1(float4 acc[16], uint32_t aB, uint32_t w1B,
                                           int wid, int lane)
{
    int arow = wid * 16 + (lane & 15);
    int aksel = (lane >> 4) << 3;
    int wrow = (lane & 7) + ((lane >> 4) & 1) * 8;
    int wksel = ((lane >> 3) & 1) << 3;

    #pragma unroll
    for (int kc = 0; kc < 2; ++kc) {
        int ak = kc * 16 + aksel;
        uint32_t aOff = SWZ128((uint32_t)(arow * 128 + ak * 2));
        uint32_t ah0, ah1, ah2, ah3;
        LDMX4(ah0, ah1, ah2, ah3, aB + aOff);

        int wk = kc * 16 + wksel;
        #pragma unroll
        for (int gq = 0; gq < 4; ++gq) {
            int n0 = gq * 32 + wrow;
            uint32_t w0 = w1B + SWZ64((uint32_t)(n0 * 64 + wk * 2));
            uint32_t w1 = w1B + SWZ64((uint32_t)((n0 + 16) * 64 + wk * 2));
            uint32_t h0, h1, h2, h3, h4, h5, h6, h7;
            uint32_t l0, l1, l2, l3, l4, l5, l6, l7;
            LDMX4(h0, h1, h2, h3, w0);
            LDMX4(h4, h5, h6, h7, w1);
            LDMX4(l0, l1, l2, l3, w0 + 8192);
            LDMX4(l4, l5, l6, l7, w1 + 8192);
            MMA(acc[4 * gq + 0], ah0, ah1, ah2, ah3, h0, h1);
            MMA(acc[4 * gq + 1], ah0, ah1, ah2, ah3, h2, h3);
            MMA(acc[4 * gq + 2], ah0, ah1, ah2, ah3, h4, h5);
            MMA(acc[4 * gq + 3], ah0, ah1, ah2, ah3, h6, h7);
            MMA(acc[4 * gq + 0], ah0, ah1, ah2, ah3, l0, l1);
            MMA(acc[4 * gq + 1], ah0, ah1, ah2, ah3, l2, l3);
            MMA(acc[4 * gq + 2], ah0, ah1, ah2, ah3, l4, l5);
            MMA(acc[4 * gq + 3], ah0, ah1, ah2, ah3, l6, l7);
        }
    }
}

// epilogue: bias + relu -> bf16 A tile (next layer input, SW128 layout)
__device__ __forceinline__ void epi_to_A(float4 acc[16], char* smA, const float* bias,
                                         int wid, int lane)
{
    int g = lane >> 2, tig = lane & 3;
    int row0 = wid * 16 + g;
    #pragma unroll
    for (int nt = 0; nt < 16; ++nt) {
        int n0 = nt * 8 + tig * 2;
        float b0v = bias[n0], b1v = bias[n0 + 1];
        float v00 = fmaxf(acc[nt].x + b0v, 0.f);
        float v01 = fmaxf(acc[nt].y + b1v, 0.f);
        float v10 = fmaxf(acc[nt].z + b0v, 0.f);
        float v11 = fmaxf(acc[nt].w + b1v, 0.f);
        uint32_t sub = (uint32_t)((n0 >> 6) * 16384);
        uint32_t o0 = sub + SWZ128((uint32_t)(row0 * 128 + (n0 & 63) * 2));
        uint32_t o1 = sub + SWZ128((uint32_t)((row0 + 8) * 128 + (n0 & 63) * 2));
        *(__nv_bfloat162*)(smA + o0) = __floats2bfloat162_rn(v00, v01);
        *(__nv_bfloat162*)(smA + o1) = __floats2bfloat162_rn(v10, v11);
    }
}

// final epilogue: bias + relu -> linear bf16 staging [128][128]
__device__ __forceinline__ void epi_stage(float4 acc[16], char* stg, const float* bias,
                                          int wid, int lane)
{
    int g = lane >> 2, tig = lane & 3;
    int row0 = wid * 16 + g;
    #pragma unroll
    for (int nt = 0; nt < 16; ++nt) {
        int n0 = nt * 8 + tig * 2;
        float b0v = bias[n0], b1v = bias[n0 + 1];
        float v00 = fmaxf(acc[nt].x + b0v, 0.f);
        float v01 = fmaxf(acc[nt].y + b1v, 0.f);
        float v10 = fmaxf(acc[nt].z + b0v, 0.f);
        float v11 = fmaxf(acc[nt].w + b1v, 0.f);
        *(__nv_bfloat162*)(stg + (row0 * 128 + n0) * 2)       = __floats2bfloat162_rn(v00, v01);
        *(__nv_bfloat162*)(stg + ((row0 + 8) * 128 + n0) * 2) = __floats2bfloat162_rn(v10, v11);
    }
}

// ============================================================================
// k_pre: weight images (blocks 0..143) + demo encoder (144..151) + We (152)
// (psi branch dead: agg-dependent key term is constant over t, cancels in softmax)
// ============================================================================
__global__ void k_pre(const float* __restrict__ demo,
                      const float* __restrict__ dw1, const float* __restrict__ db1,
                      const float* __restrict__ dw2, const float* __restrict__ db2,
                      const float* __restrict__ Wk, const float* __restrict__ Wq,
                      const float* __restrict__ pw1, const float* __restrict__ pw2,
                      const float* __restrict__ pw3)
{
    int tid = threadIdx.x;
    if (blockIdx.x < 144) {
        int idx = blockIdx.x * 256 + tid;
        float val; char* dh; char* dl; uint32_t off;
        if (idx < 4096) {                    // W1: SW64 [128 n][32 k]
            int nn = idx >> 5, k = idx & 31;
            val = pw1[k * 128 + nn];
            off = SWZ64((uint32_t)(nn * 64 + k * 2));
            dh = (char*)g_W1h; dl = (char*)g_W1l;
        } else if (idx < 20480) {            // W2
            int j = idx - 4096; int s = j >> 13, r = j & 8191;
            int nn = r >> 6, k = r & 63;
            val = pw2[(s * 64 + k) * 128 + nn];
            off = s * 16384 + SWZ128((uint32_t)(nn * 128 + k * 2));
            dh = (char*)g_W2h; dl = (char*)g_W2l;
        } else {                             // W3
            int j = idx - 20480; int s = j >> 13, r = j & 8191;
            int nn = r >> 6, k = r & 63;
            val = pw3[(s * 64 + k) * 128 + nn];
            off = s * 16384 + SWZ128((uint32_t)(nn * 128 + k * 2));
            dh = (char*)g_W3h; dl = (char*)g_W3l;
        }
        __nv_bfloat16 h = __float2bfloat16(val);
        __nv_bfloat16 l = __float2bfloat16(val - __bfloat162float(h));
        *(__nv_bfloat16*)(dh + off) = h;
        *(__nv_bfloat16*)(dl + off) = l;
        return;
    }
    if (blockIdx.x == 152) {                 // effective attention weights
        if (tid < 128) {
            int ii = tid >> 2, h = tid & 3;
            float acc = 0.f;
            for (int d = 0; d < 64; ++d)
                acc = fmaf(Wk[ii * 256 + h * 64 + d], Wq[h * 64 + d], acc);
            g_We[ii * 4 + h] = acc * 0.125f;
        }
        return;
    }
    // demo encoder: 8 batch rows per block
    int b0 = (blockIdx.x - 144) * 8;
    __shared__ float sd[64];
    __shared__ float sh[8 * 128];
    for (int i = tid; i < 64; i += 256) sd[i] = demo[b0 * 8 + i];
    __syncthreads();
    for (int i = tid; i < 1024; i += 256) {
        int bl = i >> 7, j = i & 127;
        float acc = db1[j];
        #pragma unroll
        for (int k = 0; k < 8; ++k) acc = fmaf(sd[bl * 8 + k], dw1[k * 128 + j], acc);
        sh[i] = fmaxf(acc, 0.f);
    }
    __syncthreads();
    {
        int bl = tid >> 5, f = tid & 31;
        float acc = db2[f];
        for (int k = 0; k < 128; ++k) acc = fmaf(sh[bl * 128 + k], dw2[k * 32 + f], acc);
        g_demo_enc[(b0 + bl) * 32 + f] = acc;
    }
}

// ============================================================================
// k_encode: 128 tokens/block, 256 threads, 2 CTAs/SM. W1 prefetched into the
// (dead-during-layer-1) A subtile1; W2 prefetched into the W buffer from block
// start (hidden behind features+scores+layer1); W3 issued after layer-2 mainloop.
// Online softmax partials (flash-style).
// ============================================================================
__global__ __launch_bounds__(256, 2)
void k_encode(const float* __restrict__ times, const float* __restrict__ values,
              const int* __restrict__ meas, const int* __restrict__ lengths,
              const float* __restrict__ pb1, const float* __restrict__ pb2,
              const float* __restrict__ pb3)
{
    int b = blockIdx.y;
    int tile = blockIdx.x;
    int token0 = tile * 128;
    int nvalid = lengths[b] + 1;
    if (token0 >= nvalid) return;

    extern __shared__ char sm[];
    char* smA = sm;             // 32KB: A tile / final staging; subtile1 hosts W1 early
    char* smW = sm + 32768;     // 64KB: W2 then W3 (hi / lo at +32768)
    uint32_t aB = smem_u32(smA), wB = smem_u32(smW);
    uint32_t w1B = aB + 16384;  // W1 hi; lo at +8192
    __shared__ float b1s[128], b2s[128], b3s[128], WeS[128], tsS[8];
    __shared__ float sw[512];   // scores [4][128] -> reused as softmax weights
    __shared__ float MZ[8];

    int tid = threadIdx.x, wid = tid >> 5, lane = tid & 31;

    // ---- prefetch W1 (group0) into A subtile1; W2 (group1) into W buffer ----
    {
        const char* s1h = (const char*)g_W1h;
        const char* s1l = (const char*)g_W1l;
        #pragma unroll
        for (int u = 0; u < 2; ++u) {
            int i = tid + u * 256;           // 0..511 (8KB each)
            CP_ASYNC16(w1B + i * 16,        s1h + i * 16);
            CP_ASYNC16(w1B + 8192 + i * 16, s1l + i * 16);
        }
        CP_COMMIT();
        const char* s2h = (const char*)g_W2h;
        const char* s2l = (const char*)g_W2l;
        #pragma unroll
        for (int u = 0; u < 8; ++u) {
            int i = tid + u * 256;           // 0..2047 (32KB each)
            CP_ASYNC16(wB + i * 16,         s2h + i * 16);
            CP_ASYNC16(wB + 32768 + i * 16, s2l + i * 16);
        }
        CP_COMMIT();
    }

    if (tid < 8) tsS[tid] = (float)exp(((double)tid / 7.0) * 4.605170185988091368);
    __syncthreads();

    // ---- features (tid<128, into A subtile0) / biases + We (tid>=128) ----
    float x[32];
    if (tid < 128) {
        int m = tid, tg = token0 + m;
        if (tg == 0) {
            #pragma unroll
            for (int f = 0; f < 32; ++f) x[f] = g_demo_enc[b * 32 + f];
        } else {
            size_t idx = (size_t)b * T + (tg - 1);
            float tv = times[idx];
            float vv = values[idx];
            int mm = meas[idx];
            #pragma unroll
            for (int i = 0; i < 8; ++i) {
                float sc = tv / tsS[i];
                x[i] = sinf(sc);
                x[i + 8] = cosf(sc);
            }
            x[16] = vv;
            #pragma unroll
            for (int j = 0; j < 15; ++j) x[17 + j] = (j == mm) ? 1.f : 0.f;
        }
        #pragma unroll
        for (int g = 0; g < 4; ++g) {
            union { uint4 u; __nv_bfloat162 h[4]; } ph;
            #pragma unroll
            for (int q = 0; q < 4; ++q)
                ph.h[q] = __floats2bfloat162_rn(x[g * 8 + 2 * q], x[g * 8 + 2 * q + 1]);
            *(uint4*)(smA + SWZ128((uint32_t)(m * 128 + g * 16))) = ph.u;
        }
    } else {
        int t2 = tid - 128;
        b1s[t2] = pb1[t2];
        b2s[t2] = pb2[t2];
        b3s[t2] = pb3[t2];
        WeS[t2] = g_We[t2];
    }
    __syncthreads();

    // ---- attention scores (invalid -> -1e30) ----
    if (tid < 128) {
        int tg = token0 + tid;
        float s0 = -1e30f, s1 = -1e30f, s2 = -1e30f, s3 = -1e30f;
        if (tg < nvalid) {
            s0 = s1 = s2 = s3 = 0.f;
            #pragma unroll
            for (int f = 0; f < 32; ++f) {
                float xv = x[f];
                s0 = fmaf(xv, WeS[f * 4 + 0], s0);
                s1 = fmaf(xv, WeS[f * 4 + 1], s1);
                s2 = fmaf(xv, WeS[f * 4 + 2], s2);
                s3 = fmaf(xv, WeS[f * 4 + 3], s3);
            }
        }
        sw[0 * 128 + tid] = s0;
        sw[1 * 128 + tid] = s1;
        sw[2 * 128 + tid] = s2;
        sw[3 * 128 + tid] = s3;
    }

    CP_WAIT(1);                      // W1 resident (W2 may still fly)
    __syncthreads();

    float4 acc[16];

    // ---- layer 1 (K=32): A subtile0 x W1 (SW64, in A subtile1) ----
    #pragma unroll
    for (int i = 0; i < 16; ++i) acc[i] = make_float4(0.f, 0.f, 0.f, 0.f);
    mma_layer1(acc, aB, w1B, wid, lane);
    __syncthreads();                 // all W1 reads done; A may be rewritten
    epi_to_A(acc, smA, b1s, wid, lane);
    CP_WAIT(0);                      // W2 resident
    __syncthreads();

    // ---- layer 2 (K=128) ----
    #pragma unroll
    for (int i = 0; i < 16; ++i) acc[i] = make_float4(0.f, 0.f, 0.f, 0.f);
    mma_layer(acc, aB, wB, wid, lane, 8);
    __syncthreads();                 // all W2 reads done; W buffer reusable
    {   // prefetch W3 into the W buffer, overlapped with layer-2 epilogue
        const char* s3h = (const char*)g_W3h;
        const char* s3l = (const char*)g_W3l;
        #pragma unroll
        for (int u = 0; u < 8; ++u) {
            int i = tid + u * 256;
            CP_ASYNC16(wB + i * 16,         s3h + i * 16);
            CP_ASYNC16(wB + 32768 + i * 16, s3l + i * 16);
        }
        CP_COMMIT();
    }
    epi_to_A(acc, smA, b2s, wid, lane);
    CP_WAIT(0);                      // W3 resident
    __syncthreads();

    // ---- layer 3 (K=128) -> staging ----
    #pragma unroll
    for (int i = 0; i < 16; ++i) acc[i] = make_float4(0.f, 0.f, 0.f, 0.f);
    mma_layer(acc, aB, wB, wid, lane, 8);
    __syncthreads();
    epi_stage(acc, smA, b3s, wid, lane);     // linear bf16 [128][128]
    __syncthreads();

    // ---- online softmax partials ----
    int tcnt = min(128, nvalid - token0);
    if (wid < 4) {                   // warp w handles head w; sw -> weights in place
        int h = wid;
        float m = -1e30f;
        #pragma unroll
        for (int u = 0; u < 4; ++u) m = fmaxf(m, sw[h * 128 + u * 32 + lane]);
        #pragma unroll
        for (int off = 16; off; off >>= 1) m = fmaxf(m, __shfl_xor_sync(~0u, m, off));
        float z = 0.f;
        #pragma unroll
        for (int u = 0; u < 4; ++u) {
            int t = u * 32 + lane;
            float w = (t < tcnt) ? expf(sw[h * 128 + t] - m) : 0.f;
            sw[h * 128 + t] = w;
            z += w;
        }
        #pragma unroll
        for (int off = 16; off; off >>= 1) z += __shfl_xor_sync(~0u, z, off);
        if (lane == 0) { MZ[h] = m; MZ[4 + h] = z; }
    }
    __syncthreads();
    {
        int h = tid >> 6, c = tid & 63;      // thread: head h, bf162 column c
        const __nv_bfloat162* eb = (const __nv_bfloat162*)smA + c;
        float ax = 0.f, ay = 0.f;
        for (int t = 0; t < tcnt; ++t) {
            float2 ef = __bfloat1622float2(eb[t * 64]);
            float w = sw[h * 128 + t];
            ax = fmaf(w, ef.x, ax);
            ay = fmaf(w, ef.y, ay);
        }
        float* dst = g_pS + (((size_t)b * 32 + tile) * 4 + h) * 128;
        dst[2 * c]     = ax;
        dst[2 * c + 1] = ay;
        if (tid < 8) g_pMZ[(b * 32 + tile) * 8 + tid] = MZ[tid];
    }
}

// ============================================================================
// k_fin: combine per-tile partials (rescaled) -> feat, then rho MLP
// 512 -> 128 -> 128 -> 1 + sigmoid; split-K over 4 partitions.
// ============================================================================
__global__ __launch_bounds__(512)
void k_fin(const int* __restrict__ lengths,
           const float* __restrict__ rw1, const float* __restrict__ rb1,
           const float* __restrict__ rw2, const float* __restrict__ rb2,
           const float* __restrict__ rw3, const float* __restrict__ rb3,
           float* __restrict__ out)
{
    int b = blockIdx.x, tid = threadIdx.x;
    int ntiles = (lengths[b] + 128) >> 7;       // ceil((len+1)/128)
    __shared__ float sM[128], sZ[128];          // 32 tiles x 4 heads
    __shared__ float Mg[4], Zg[4];
    __shared__ float sf[512];
    __shared__ float red[512];
    __shared__ float sh1[128];

    for (int i = tid; i < ntiles * 8; i += 512) {
        int t = i >> 3, j = i & 7;
        float v = g_pMZ[(b * 32 + t) * 8 + j];
        if (j < 4) sM[t * 4 + j] = v;
        else       sZ[t * 4 + (j - 4)] = v;
    }
    __syncthreads();
    if (tid < 4) {
        float m = -1e30f;
        for (int t = 0; t < ntiles; ++t) m = fmaxf(m, sM[t * 4 + tid]);
        float z = 0.f;
        for (int t = 0; t < ntiles; ++t) z += expf(sM[t * 4 + tid] - m) * sZ[t * 4 + tid];
        Mg[tid] = m;
        Zg[tid] = 1.f / z;
    }
    __syncthreads();

    {   // combine: thread = (head h, lane l)
        int h = tid >> 7, l = tid & 127;
        float mg = Mg[h];
        float acc = 0.f;
        for (int t = 0; t < ntiles; ++t) {
            float f = expf(sM[t * 4 + h] - mg);
            acc = fmaf(f, g_pS[(((size_t)b * 32 + t) * 4 + h) * 128 + l], acc);
        }
        sf[h * 128 + l] = acc * Zg[h];
    }
    __syncthreads();

    int j = tid & 127, p = tid >> 7;
    {   // rho layer 1 (512->128), split-K x4
        float a1 = 0.f;
        const float* w = rw1 + (p * 128) * 128 + j;
        const float* f = sf + p * 128;
        #pragma unroll 8
        for (int i = 0; i < 128; ++i) a1 = fmaf(f[i], w[i * 128], a1);
        red[tid] = a1;
    }
    __syncthreads();
    if (tid < 128)
        sh1[tid] = fmaxf(red[tid] + red[tid + 128] + red[tid + 256] + red[tid + 384]
                         + rb1[tid], 0.f);
    __syncthreads();
    {   // rho layer 2 (128->128), split-K x4
        float a2 = 0.f;
        const float* w = rw2 + (p * 32) * 128 + j;
        const float* f = sh1 + p * 32;
        #pragma unroll 8
        for (int i = 0; i < 32; ++i) a2 = fmaf(f[i], w[i * 128], a2);
        red[tid] = a2;
    }
    __syncthreads();
    if (tid < 128) {
        float h2 = fmaxf(red[tid] + red[tid + 128] + red[tid + 256] + red[tid + 384]
                         + rb2[tid], 0.f);
        red[tid] = h2 * rw3[tid];
    }
    __syncthreads();
    for (int off = 64; off > 0; off >>= 1) {
        if (tid < off) red[tid] += red[tid + off];
        __syncthreads();
    }
    if (tid == 0) out[b] = 1.f / (1.f + expf(-(red[0] + rb3[0])));
}

// ============================================================================
extern "C" void kernel_launch(void* const* d_in, const int* in_sizes, int n_in,
                              void* d_out, int out_size)
{
    const float* demo    = (const float*)d_in[0];
    const float* times   = (const float*)d_in[1];
    const float* values  = (const float*)d_in[2];
    const int*   meas    = (const int*)  d_in[3];
    const int*   lengths = (const int*)  d_in[4];
    const float* dw1 = (const float*)d_in[5];
    const float* db1 = (const float*)d_in[6];
    const float* dw2 = (const float*)d_in[7];
    const float* db2 = (const float*)d_in[8];
    const float* pw1 = (const float*)d_in[9];
    const float* pb1 = (const float*)d_in[10];
    const float* pw2 = (const float*)d_in[11];
    const float* pb2 = (const float*)d_in[12];
    const float* pw3 = (const float*)d_in[13];
    const float* pb3 = (const float*)d_in[14];
    // d_in[15..22]: psi / rho_attn params — dead (softmax-constant), unused
    const float* Wk  = (const float*)d_in[23];
    const float* Wq  = (const float*)d_in[24];
    const float* rw1 = (const float*)d_in[25];
    const float* rb1 = (const float*)d_in[26];
    const float* rw2 = (const float*)d_in[27];
    const float* rb2 = (const float*)d_in[28];
    const float* rw3 = (const float*)d_in[29];
    const float* rb3 = (const float*)d_in[30];
    float* out = (float*)d_out;

    const int SMEM_BYTES = 98304;      // A(32KB) + W(64KB); 2 CTAs/SM
    cudaFuncSetAttribute(k_encode, cudaFuncAttributeMaxDynamicSharedMemorySize, SMEM_BYTES);

    k_pre<<<153, 256>>>(demo, dw1, db1, dw2, db2, Wk, Wq, pw1, pw2, pw3);
    k_encode<<<dim3(32, B), 256, SMEM_BYTES>>>(times, values, meas, lengths, pb1, pb2, pb3);
    k_fin<<<B, 512>>>(lengths, rw1, rb1, rw2, rb2, rw3, rb3, out);
}

// round 15
// speedup vs baseline: 1.0192x; 1.0192x over previous
#include <cuda_runtime.h>
#include <cuda_bf16.h>
#include <math.h>
#include <stdint.h>

#define B 64
#define T 4096

// ---------------- device scratch (static only) ----------------
__device__ float g_demo_enc[B * 32];
__device__ float g_We[32 * 4];
__device__ float g_pS[(size_t)B * 32 * 4 * 128];       // per-tile partial sums (4MB)
__device__ float g_pMZ[B * 32 * 8];                    // per-tile {M[4], Z[4]}
// W1: SW64 image [128 n][32 k] (64B rows); W2/W3: SW128 images, 2 k-subtiles
__device__ __align__(16) __nv_bfloat16 g_W1h[4096],  g_W1l[4096];
__device__ __align__(16) __nv_bfloat16 g_W2h[16384], g_W2l[16384];
__device__ __align__(16) __nv_bfloat16 g_W3h[16384], g_W3l[16384];

// ---------------- helpers ----------------
__device__ __forceinline__ uint32_t smem_u32(const void* p) {
    uint32_t a;
    asm("{ .reg .u64 t; cvta.to.shared.u64 t, %1; cvt.u32.u64 %0, t; }" : "=r"(a) : "l"(p));
    return a;
}
#define SWZ128(o) ((o) ^ (((o) >> 3) & 0x70))
#define SWZ64(o)  ((o) ^ (((o) >> 3) & 0x30))

#define LDMX4(r0, r1, r2, r3, a) \
    asm volatile("ldmatrix.sync.aligned.m8n8.x4.shared.b16 {%0,%1,%2,%3}, [%4];" \
                 : "=r"(r0), "=r"(r1), "=r"(r2), "=r"(r3) : "r"(a))

#define MMA(d, a0, a1, a2, a3, b0, b1) \
    asm volatile("mma.sync.aligned.m16n8k16.row.col.f32.bf16.bf16.f32 " \
                 "{%0,%1,%2,%3}, {%4,%5,%6,%7}, {%8,%9}, {%0,%1,%2,%3};" \
                 : "+f"((d).x), "+f"((d).y), "+f"((d).z), "+f"((d).w) \
                 : "r"(a0), "r"(a1), "r"(a2), "r"(a3), "r"(b0), "r"(b1))

#define CP_ASYNC16(sma, gp) \
    asm volatile("cp.async.cg.shared.global [%0], [%1], 16;" :: "r"(sma), "l"(gp))
#define CP_COMMIT() asm volatile("cp.async.commit_group;" ::: "memory")
#define CP_WAIT(n)  asm volatile("cp.async.wait_group %0;" :: "n"(n) : "memory")

// A tile (128 rows): bf16, 2 k-subtiles of 16KB; elem (row,k) at
//   sub*16384 + SWZ128(row*128 + (k&63)*2).
// W2/W3 tile: hi at base (2 subtiles of 16KB), lo at +32768.
// W1 tile (in A subtile1 during layer 1): 64B rows, SW64; hi at base, lo at +8192.

// ---- GEMM layer on SW128 W: acc[16] += A(128xK) @ (Wh+Wl) ----
__device__ __forceinline__ void mma_layer(float4 acc[16], uint32_t aB, uint32_t wB,
                                          int wid, int lane, int kchunks)
{
    int arow = wid * 16 + (lane & 15);
    int aksel = (lane >> 4) << 3;
    int wrow = (lane & 7) + ((lane >> 4) & 1) * 8;
    int wksel = ((lane >> 3) & 1) << 3;

    for (int kc = 0; kc < kchunks; ++kc) {
        int ak = kc * 16 + aksel;
        uint32_t aOff = (uint32_t)((ak >> 6) * 16384) +
                        SWZ128((uint32_t)(arow * 128 + (ak & 63) * 2));
        uint32_t ah0, ah1, ah2, ah3;
        LDMX4(ah0, ah1, ah2, ah3, aB + aOff);

        int wk = kc * 16 + wksel;
        uint32_t wsub = (uint32_t)((wk >> 6) * 16384);
        uint32_t wko = (uint32_t)((wk & 63) * 2);

        #pragma unroll
        for (int gq = 0; gq < 4; ++gq) {
            int n0 = gq * 32 + wrow;
            uint32_t w0 = wB + wsub + SWZ128((uint32_t)(n0 * 128) + wko);
            uint32_t w1 = wB + wsub + SWZ128((uint32_t)((n0 + 16) * 128) + wko);
            uint32_t h0, h1, h2, h3, h4, h5, h6, h7;
            uint32_t l0, l1, l2, l3, l4, l5, l6, l7;
            LDMX4(h0, h1, h2, h3, w0);
            LDMX4(h4, h5, h6, h7, w1);
            LDMX4(l0, l1, l2, l3, w0 + 32768);
            LDMX4(l4, l5, l6, l7, w1 + 32768);
            MMA(acc[4 * gq + 0], ah0, ah1, ah2, ah3, h0, h1);
            MMA(acc[4 * gq + 1], ah0, ah1, ah2, ah3, h2, h3);
            MMA(acc[4 * gq + 2], ah0, ah1, ah2, ah3, h4, h5);
            MMA(acc[4 * gq + 3], ah0, ah1, ah2, ah3, h6, h7);
            MMA(acc[4 * gq + 0], ah0, ah1, ah2, ah3, l0, l1);
            MMA(acc[4 * gq + 1], ah0, ah1, ah2, ah3, l2, l3);
            MMA(acc[4 * gq + 2], ah0, ah1, ah2, ah3, l4, l5);
            MMA(acc[4 * gq + 3], ah0, ah1, ah2, ah3, l6, l7);
        }
    }
}

// ---- layer-1 GEMM on SW64 compact W1 (K=32) ----
__device__ __forceinline__ void mma_layer1(float4 acc[16], uint32_t aB, uint32_t w1B,
                                           int wid, int lane)
{
    int arow = wid * 16 + (lane & 15);
    int aksel = (lane >> 4) << 3;
    int wrow = (lane & 7) + ((lane >> 4) & 1) * 8;
    int wksel = ((lane >> 3) & 1) << 3;

    #pragma unroll
    for (int kc = 0; kc < 2; ++kc) {
        int ak = kc * 16 + aksel;
        uint32_t aOff = SWZ128((uint32_t)(arow * 128 + ak * 2));
        uint32_t ah0, ah1, ah2, ah3;
        LDMX4(ah0, ah1, ah2, ah3, aB + aOff);

        int wk = kc * 16 + wksel;
        #pragma unroll
        for (int gq = 0; gq < 4; ++gq) {
            int n0 = gq * 32 + wrow;
            uint32_t w0 = w1B + SWZ64((uint32_t)(n0 * 64 + wk * 2));
            uint32_t w1 = w1B + SWZ64((uint32_t)((n0 + 16) * 64 + wk * 2));
            uint32_t h0, h1, h2, h3, h4, h5, h6, h7;
            uint32_t l0, l1, l2, l3, l4, l5, l6, l7;
            LDMX4(h0, h1, h2, h3, w0);
            LDMX4(h4, h5, h6, h7, w1);
            LDMX4(l0, l1, l2, l3, w0 + 8192);
            LDMX4(l4, l5, l6, l7, w1 + 8192);
            MMA(acc[4 * gq + 0], ah0, ah1, ah2, ah3, h0, h1);
            MMA(acc[4 * gq + 1], ah0, ah1, ah2, ah3, h2, h3);
            MMA(acc[4 * gq + 2], ah0, ah1, ah2, ah3, h4, h5);
            MMA(acc[4 * gq + 3], ah0, ah1, ah2, ah3, h6, h7);
            MMA(acc[4 * gq + 0], ah0, ah1, ah2, ah3, l0, l1);
            MMA(acc[4 * gq + 1], ah0, ah1, ah2, ah3, l2, l3);
            MMA(acc[4 * gq + 2], ah0, ah1, ah2, ah3, l4, l5);
            MMA(acc[4 * gq + 3], ah0, ah1, ah2, ah3, l6, l7);
        }
    }
}

// epilogue: bias + relu -> bf16 A tile (next layer input, SW128 layout)
__device__ __forceinline__ void epi_to_A(float4 acc[16], char* smA, const float* bias,
                                         int wid, int lane)
{
    int g = lane >> 2, tig = lane & 3;
    int row0 = wid * 16 + g;
    #pragma unroll
    for (int nt = 0; nt < 16; ++nt) {
        int n0 = nt * 8 + tig * 2;
        float b0v = bias[n0], b1v = bias[n0 + 1];
        float v00 = fmaxf(acc[nt].x + b0v, 0.f);
        float v01 = fmaxf(acc[nt].y + b1v, 0.f);
        float v10 = fmaxf(acc[nt].z + b0v, 0.f);
        float v11 = fmaxf(acc[nt].w + b1v, 0.f);
        uint32_t sub = (uint32_t)((n0 >> 6) * 16384);
        uint32_t o0 = sub + SWZ128((uint32_t)(row0 * 128 + (n0 & 63) * 2));
        uint32_t o1 = sub + SWZ128((uint32_t)((row0 + 8) * 128 + (n0 & 63) * 2));
        *(__nv_bfloat162*)(smA + o0) = __floats2bfloat162_rn(v00, v01);
        *(__nv_bfloat162*)(smA + o1) = __floats2bfloat162_rn(v10, v11);
    }
}

// final epilogue: bias + relu -> linear bf16 staging [128][128]
__device__ __forceinline__ void epi_stage(float4 acc[16], char* stg, const float* bias,
                                          int wid, int lane)
{
    int g = lane >> 2, tig = lane & 3;
    int row0 = wid * 16 + g;
    #pragma unroll
    for (int nt = 0; nt < 16; ++nt) {
        int n0 = nt * 8 + tig * 2;
        float b0v = bias[n0], b1v = bias[n0 + 1];
        float v00 = fmaxf(acc[nt].x + b0v, 0.f);
        float v01 = fmaxf(acc[nt].y + b1v, 0.f);
        float v10 = fmaxf(acc[nt].z + b0v, 0.f);
        float v11 = fmaxf(acc[nt].w + b1v, 0.f);
        *(__nv_bfloat162*)(stg + (row0 * 128 + n0) * 2)       = __floats2bfloat162_rn(v00, v01);
        *(__nv_bfloat162*)(stg + ((row0 + 8) * 128 + n0) * 2) = __floats2bfloat162_rn(v10, v11);
    }
}

// ============================================================================
// k_pre: weight images (blocks 0..143) + demo encoder (144..151) + We (152)
// (psi branch dead: agg-dependent key term is constant over t, cancels in softmax)
// ============================================================================
__global__ void k_pre(const float* __restrict__ demo,
                      const float* __restrict__ dw1, const float* __restrict__ db1,
                      const float* __restrict__ dw2, const float* __restrict__ db2,
                      const float* __restrict__ Wk, const float* __restrict__ Wq,
                      const float* __restrict__ pw1, const float* __restrict__ pw2,
                      const float* __restrict__ pw3)
{
    int tid = threadIdx.x;
    if (blockIdx.x < 144) {
        int idx = blockIdx.x * 256 + tid;
        float val; char* dh; char* dl; uint32_t off;
        if (idx < 4096) {                    // W1: SW64 [128 n][32 k]
            int nn = idx >> 5, k = idx & 31;
            val = pw1[k * 128 + nn];
            off = SWZ64((uint32_t)(nn * 64 + k * 2));
            dh = (char*)g_W1h; dl = (char*)g_W1l;
        } else if (idx < 20480) {            // W2
            int j = idx - 4096; int s = j >> 13, r = j & 8191;
            int nn = r >> 6, k = r & 63;
            val = pw2[(s * 64 + k) * 128 + nn];
            off = s * 16384 + SWZ128((uint32_t)(nn * 128 + k * 2));
            dh = (char*)g_W2h; dl = (char*)g_W2l;
        } else {                             // W3
            int j = idx - 20480; int s = j >> 13, r = j & 8191;
            int nn = r >> 6, k = r & 63;
            val = pw3[(s * 64 + k) * 128 + nn];
            off = s * 16384 + SWZ128((uint32_t)(nn * 128 + k * 2));
            dh = (char*)g_W3h; dl = (char*)g_W3l;
        }
        __nv_bfloat16 h = __float2bfloat16(val);
        __nv_bfloat16 l = __float2bfloat16(val - __bfloat162float(h));
        *(__nv_bfloat16*)(dh + off) = h;
        *(__nv_bfloat16*)(dl + off) = l;
        return;
    }
    if (blockIdx.x == 152) {                 // effective attention weights
        if (tid < 128) {
            int ii = tid >> 2, h = tid & 3;
            float acc = 0.f;
            for (int d = 0; d < 64; ++d)
                acc = fmaf(Wk[ii * 256 + h * 64 + d], Wq[h * 64 + d], acc);
            g_We[ii * 4 + h] = acc * 0.125f;
        }
        return;
    }
    // demo encoder: 8 batch rows per block
    int b0 = (blockIdx.x - 144) * 8;
    __shared__ float sd[64];
    __shared__ float sh[8 * 128];
    for (int i = tid; i < 64; i += 256) sd[i] = demo[b0 * 8 + i];
    __syncthreads();
    for (int i = tid; i < 1024; i += 256) {
        int bl = i >> 7, j = i & 127;
        float acc = db1[j];
        #pragma unroll
        for (int k = 0; k < 8; ++k) acc = fmaf(sd[bl * 8 + k], dw1[k * 128 + j], acc);
        sh[i] = fmaxf(acc, 0.f);
    }
    __syncthreads();
    {
        int bl = tid >> 5, f = tid & 31;
        float acc = db2[f];
        for (int k = 0; k < 128; ++k) acc = fmaf(sh[bl * 128 + k], dw2[k * 32 + f], acc);
        g_demo_enc[(b0 + bl) * 32 + f] = acc;
    }
}

// ============================================================================
// k_encode: 128 tokens/block, 256 threads, 2 CTAs/SM. W1 prefetched into the
// (dead-during-layer-1) A subtile1; W2 prefetched into the W buffer from block
// start (hidden behind features+scores+layer1); W3 issued after layer-2 mainloop.
// Online softmax partials (flash-style).
// ============================================================================
__global__ __launch_bounds__(256, 2)
void k_encode(const float* __restrict__ times, const float* __restrict__ values,
              const int* __restrict__ meas, const int* __restrict__ lengths,
              const float* __restrict__ pb1, const float* __restrict__ pb2,
              const float* __restrict__ pb3)
{
    int b = blockIdx.y;
    int tile = blockIdx.x;
    int token0 = tile * 128;
    int nvalid = lengths[b] + 1;
    if (token0 >= nvalid) return;

    extern __shared__ char sm[];
    char* smA = sm;             // 32KB: A tile / final staging; subtile1 hosts W1 early
    char* smW = sm + 32768;     // 64KB: W2 then W3 (hi / lo at +32768)
    uint32_t aB = smem_u32(smA), wB = smem_u32(smW);
    uint32_t w1B = aB + 16384;  // W1 hi; lo at +8192
    __shared__ float b1s[128], b2s[128], b3s[128], WeS[128], tsS[8];
    __shared__ float sw[512];   // scores [4][128] -> reused as softmax weights
    __shared__ float MZ[8];

    int tid = threadIdx.x, wid = tid >> 5, lane = tid & 31;

    // ---- prefetch W1 (group0) into A subtile1; W2 (group1) into W buffer ----
    {
        const char* s1h = (const char*)g_W1h;
        const char* s1l = (const char*)g_W1l;
        #pragma unroll
        for (int u = 0; u < 2; ++u) {
            int i = tid + u * 256;           // 0..511 (8KB each)
            CP_ASYNC16(w1B + i * 16,        s1h + i * 16);
            CP_ASYNC16(w1B + 8192 + i * 16, s1l + i * 16);
        }
        CP_COMMIT();
        const char* s2h = (const char*)g_W2h;
        const char* s2l = (const char*)g_W2l;
        #pragma unroll
        for (int u = 0; u < 8; ++u) {
            int i = tid + u * 256;           // 0..2047 (32KB each)
            CP_ASYNC16(wB + i * 16,         s2h + i * 16);
            CP_ASYNC16(wB + 32768 + i * 16, s2l + i * 16);
        }
        CP_COMMIT();
    }

    if (tid < 8) tsS[tid] = (float)exp(((double)tid / 7.0) * 4.605170185988091368);
    __syncthreads();

    // ---- features (tid<128, into A subtile0) / biases + We (tid>=128) ----
    float x[32];
    if (tid < 128) {
        int m = tid, tg = token0 + m;
        if (tg == 0) {
            #pragma unroll
            for (int f = 0; f < 32; ++f) x[f] = g_demo_enc[b * 32 + f];
        } else {
            size_t idx = (size_t)b * T + (tg - 1);
            float tv = times[idx];
            float vv = values[idx];
            int mm = meas[idx];
            #pragma unroll
            for (int i = 0; i < 8; ++i) {
                float sc = tv / tsS[i];
                x[i] = sinf(sc);
                x[i + 8] = cosf(sc);
            }
            x[16] = vv;
            #pragma unroll
            for (int j = 0; j < 15; ++j) x[17 + j] = (j == mm) ? 1.f : 0.f;
        }
        #pragma unroll
        for (int g = 0; g < 4; ++g) {
            union { uint4 u; __nv_bfloat162 h[4]; } ph;
            #pragma unroll
            for (int q = 0; q < 4; ++q)
                ph.h[q] = __floats2bfloat162_rn(x[g * 8 + 2 * q], x[g * 8 + 2 * q + 1]);
            *(uint4*)(smA + SWZ128((uint32_t)(m * 128 + g * 16))) = ph.u;
        }
    } else {
        int t2 = tid - 128;
        b1s[t2] = pb1[t2];
        b2s[t2] = pb2[t2];
        b3s[t2] = pb3[t2];
        WeS[t2] = g_We[t2];
    }
    __syncthreads();

    // ---- attention scores (invalid -> -1e30) ----
    if (tid < 128) {
        int tg = token0 + tid;
        float s0 = -1e30f, s1 = -1e30f, s2 = -1e30f, s3 = -1e30f;
        if (tg < nvalid) {
            s0 = s1 = s2 = s3 = 0.f;
            #pragma unroll
            for (int f = 0; f < 32; ++f) {
                float xv = x[f];
                s0 = fmaf(xv, WeS[f * 4 + 0], s0);
                s1 = fmaf(xv, WeS[f * 4 + 1], s1);
                s2 = fmaf(xv, WeS[f * 4 + 2], s2);
                s3 = fmaf(xv, WeS[f * 4 + 3], s3);
            }
        }
        sw[0 * 128 + tid] = s0;
        sw[1 * 128 + tid] = s1;
        sw[2 * 128 + tid] = s2;
        sw[3 * 128 + tid] = s3;
    }

    CP_WAIT(1);                      // W1 resident (W2 may still fly)
    __syncthreads();

    float4 acc[16];

    // ---- layer 1 (K=32): A subtile0 x W1 (SW64, in A subtile1) ----
    #pragma unroll
    for (int i = 0; i < 16; ++i) acc[i] = make_float4(0.f, 0.f, 0.f, 0.f);
    mma_layer1(acc, aB, w1B, wid, lane);
    __syncthreads();                 // all W1 reads done; A may be rewritten
    epi_to_A(acc, smA, b1s, wid, lane);
    CP_WAIT(0);                      // W2 resident
    __syncthreads();

    // ---- layer 2 (K=128) ----
    #pragma unroll
    for (int i = 0; i < 16; ++i) acc[i] = make_float4(0.f, 0.f, 0.f, 0.f);
    mma_layer(acc, aB, wB, wid, lane, 8);
    __syncthreads();                 // all W2 reads done; W buffer reusable
    {   // prefetch W3 into the W buffer, overlapped with layer-2 epilogue
        const char* s3h = (const char*)g_W3h;
        const char* s3l = (const char*)g_W3l;
        #pragma unroll
        for (int u = 0; u < 8; ++u) {
            int i = tid + u * 256;
            CP_ASYNC16(wB + i * 16,         s3h + i * 16);
            CP_ASYNC16(wB + 32768 + i * 16, s3l + i * 16);
        }
        CP_COMMIT();
    }
    epi_to_A(acc, smA, b2s, wid, lane);
    CP_WAIT(0);                      // W3 resident
    __syncthreads();

    // ---- layer 3 (K=128) -> staging ----
    #pragma unroll
    for (int i = 0; i < 16; ++i) acc[i] = make_float4(0.f, 0.f, 0.f, 0.f);
    mma_layer(acc, aB, wB, wid, lane, 8);
    __syncthreads();
    epi_stage(acc, smA, b3s, wid, lane);     // linear bf16 [128][128]
    __syncthreads();

    // ---- online softmax partials ----
    int tcnt = min(128, nvalid - token0);
    if (wid < 4) {                   // warp w handles head w; sw -> weights in place
        int h = wid;
        float m = -1e30f;
        #pragma unroll
        for (int u = 0; u < 4; ++u) m = fmaxf(m, sw[h * 128 + u * 32 + lane]);
        #pragma unroll
        for (int off = 16; off; off >>= 1) m = fmaxf(m, __shfl_xor_sync(~0u, m, off));
        float z = 0.f;
        #pragma unroll
        for (int u = 0; u < 4; ++u) {
            int t = u * 32 + lane;
            float w = (t < tcnt) ? expf(sw[h * 128 + t] - m) : 0.f;
            sw[h * 128 + t] = w;
            z += w;
        }
        #pragma unroll
        for (int off = 16; off; off >>= 1) z += __shfl_xor_sync(~0u, z, off);
        if (lane == 0) { MZ[h] = m; MZ[4 + h] = z; }
    }
    __syncthreads();
    {
        int h = tid >> 6, c = tid & 63;      // thread: head h, bf162 column c
        const __nv_bfloat162* eb = (const __nv_bfloat162*)smA + c;
        float ax = 0.f, ay = 0.f;
        for (int t = 0; t < tcnt; ++t) {
            float2 ef = __bfloat1622float2(eb[t * 64]);
            float w = sw[h * 128 + t];
            ax = fmaf(w, ef.x, ax);
            ay = fmaf(w, ef.y, ay);
        }
        float* dst = g_pS + (((size_t)b * 32 + tile) * 4 + h) * 128;
        dst[2 * c]     = ax;
        dst[2 * c + 1] = ay;
        if (tid < 8) g_pMZ[(b * 32 + tile) * 8 + tid] = MZ[tid];
    }
}

// ============================================================================
// k_fin: combine per-tile partials (rescaled) -> feat, then rho MLP
// 512 -> 128 -> 128 -> 1 + sigmoid; split-K over 4 partitions.
// ============================================================================
__global__ __launch_bounds__(512)
void k_fin(const int* __restrict__ lengths,
           const float* __restrict__ rw1, const float* __restrict__ rb1,
           const float* __restrict__ rw2, const float* __restrict__ rb2,
           const float* __restrict__ rw3, const float* __restrict__ rb3,
           float* __restrict__ out)
{
    int b = blockIdx.x, tid = threadIdx.x;
    int ntiles = (lengths[b] + 128) >> 7;       // ceil((len+1)/128)
    __shared__ float sM[128], sZ[128];          // 32 tiles x 4 heads
    __shared__ float Mg[4], Zg[4];
    __shared__ float sf[512];
    __shared__ float red[512];
    __shared__ float sh1[128];

    for (int i = tid; i < ntiles * 8; i += 512) {
        int t = i >> 3, j = i & 7;
        float v = g_pMZ[(b * 32 + t) * 8 + j];
        if (j < 4) sM[t * 4 + j] = v;
        else       sZ[t * 4 + (j - 4)] = v;
    }
    __syncthreads();
    if (tid < 4) {
        float m = -1e30f;
        for (int t = 0; t < ntiles; ++t) m = fmaxf(m, sM[t * 4 + tid]);
        float z = 0.f;
        for (int t = 0; t < ntiles; ++t) z += expf(sM[t * 4 + tid] - m) * sZ[t * 4 + tid];
        Mg[tid] = m;
        Zg[tid] = 1.f / z;
    }
    __syncthreads();

    {   // combine: thread = (head h, lane l)
        int h = tid >> 7, l = tid & 127;
        float mg = Mg[h];
        float acc = 0.f;
        for (int t = 0; t < ntiles; ++t) {
            float f = expf(sM[t * 4 + h] - mg);
            acc = fmaf(f, g_pS[(((size_t)b * 32 + t) * 4 + h) * 128 + l], acc);
        }
        sf[h * 128 + l] = acc * Zg[h];
    }
    __syncthreads();

    int j = tid & 127, p = tid >> 7;
    {   // rho layer 1 (512->128), split-K x4
        float a1 = 0.f;
        const float* w = rw1 + (p * 128) * 128 + j;
        const float* f = sf + p * 128;
        #pragma unroll 8
        for (int i = 0; i < 128; ++i) a1 = fmaf(f[i], w[i * 128], a1);
        red[tid] = a1;
    }
    __syncthreads();
    if (tid < 128)
        sh1[tid] = fmaxf(red[tid] + red[tid + 128] + red[tid + 256] + red[tid + 384]
                         + rb1[tid], 0.f);
    __syncthreads();
    {   // rho layer 2 (128->128), split-K x4
        float a2 = 0.f;
        const float* w = rw2 + (p * 32) * 128 + j;
        const float* f = sh1 + p * 32;
        #pragma unroll 8
        for (int i = 0; i < 32; ++i) a2 = fmaf(f[i], w[i * 128], a2);
        red[tid] = a2;
    }
    __syncthreads();
    if (tid < 128) {
        float h2 = fmaxf(red[tid] + red[tid + 128] + red[tid + 256] + red[tid + 384]
                         + rb2[tid], 0.f);
        red[tid] = h2 * rw3[tid];
    }
    __syncthreads();
    for (int off = 64; off > 0; off >>= 1) {
        if (tid < off) red[tid] += red[tid + off];
        __syncthreads();
    }
    if (tid == 0) out[b] = 1.f / (1.f + expf(-(red[0] + rb3[0])));
}

// ============================================================================
extern "C" void kernel_launch(void* const* d_in, const int* in_sizes, int n_in,
                              void* d_out, int out_size)
{
    const float* demo    = (const float*)d_in[0];
    const float* times   = (const float*)d_in[1];
    const float* values  = (const float*)d_in[2];
    const int*   meas    = (const int*)  d_in[3];
    const int*   lengths = (const int*)  d_in[4];
    const float* dw1 = (const float*)d_in[5];
    const float* db1 = (const float*)d_in[6];
    const float* dw2 = (const float*)d_in[7];
    const float* db2 = (const float*)d_in[8];
    const float* pw1 = (const float*)d_in[9];
    const float* pb1 = (const float*)d_in[10];
    const float* pw2 = (const float*)d_in[11];
    const float* pb2 = (const float*)d_in[12];
    const float* pw3 = (const float*)d_in[13];
    const float* pb3 = (const float*)d_in[14];
    // d_in[15..22]: psi / rho_attn params — dead (softmax-constant), unused
    const float* Wk  = (const float*)d_in[23];
    const float* Wq  = (const float*)d_in[24];
    const float* rw1 = (const float*)d_in[25];
    const float* rb1 = (const float*)d_in[26];
    const float* rw2 = (const float*)d_in[27];
    const float* rb2 = (const float*)d_in[28];
    const float* rw3 = (const float*)d_in[29];
    const float* rb3 = (const float*)d_in[30];
    float* out = (float*)d_out;

    const int SMEM_BYTES = 98304;      // A(32KB) + W(64KB); 2 CTAs/SM
    cudaFuncSetAttribute(k_encode, cudaFuncAttributeMaxDynamicSharedMemorySize, SMEM_BYTES);

    k_pre<<<153, 256>>>(demo, dw1, db1, dw2, db2, Wk, Wq, pw1, pw2, pw3);
    k_encode<<<dim3(32, B), 256, SMEM_BYTES>>>(times, values, meas, lengths, pb1, pb2, pb3);
    k_fin<<<B, 512>>>(lengths, rw1, rb1, rw2, rb2, rw3, rb3, out);
}